// round 9
// baseline (speedup 1.0000x reference)
#include <cuda_runtime.h>
#include <cuda_fp16.h>
#include <cstdint>
#include <math.h>

#define DM 2048
#define DF 8192
#define NT 8192

// ---------------- scratch ----------------
__device__ __align__(256) __half g_X[(size_t)NT * DM];
__device__ __align__(256) __half g_H[(size_t)NT * 2 * DF];     // [NT][2*DF], gate pre-scaled
__device__ __align__(256) __half g_W1t[2][(size_t)DF * DM];    // contiguous: [2*DF][DM]
__device__ __align__(256) __half g_W2t[2][(size_t)DM * DF];
__device__ float g_gate[2 * NT];

// ---------------- helpers ----------------
__device__ __forceinline__ uint32_t smem_u32(const void* p) {
    uint32_t a;
    asm("{ .reg .u64 t; cvta.to.shared.u64 t, %1; cvt.u32.u64 %0, t; }" : "=r"(a) : "l"(p));
    return a;
}
#define CP_ASYNC16(sa, g) \
    asm volatile("cp.async.cg.shared.global [%0], [%1], 16;" :: "r"(sa), "l"(g))
#define CP_COMMIT() asm volatile("cp.async.commit_group;" ::: "memory")
#define CP_WAIT(n)  asm volatile("cp.async.wait_group %0;" :: "n"(n) : "memory")

#define LDSM_X4(r0, r1, r2, r3, a) \
    asm volatile("ldmatrix.sync.aligned.m8n8.x4.shared.b16 {%0,%1,%2,%3}, [%4];" \
                 : "=r"(r0), "=r"(r1), "=r"(r2), "=r"(r3) : "r"(a))

__device__ __forceinline__ void mma16816(float* d, const uint32_t* a, const uint32_t* b) {
    asm volatile(
        "mma.sync.aligned.m16n8k16.row.col.f32.f16.f16.f32 "
        "{%0,%1,%2,%3}, {%4,%5,%6,%7}, {%8,%9}, {%0,%1,%2,%3};"
        : "+f"(d[0]), "+f"(d[1]), "+f"(d[2]), "+f"(d[3])
        : "r"(a[0]), "r"(a[1]), "r"(a[2]), "r"(a[3]), "r"(b[0]), "r"(b[1]));
}

// 128B rows, 8x 16B segments, XOR swizzle
__device__ __forceinline__ uint32_t swz(uint32_t r, uint32_t s) {
    return (r << 7) + ((s ^ (r & 7)) << 4);
}
__device__ __forceinline__ uint32_t pack_h2(float a, float b) {
    __half2 v = __floats2half2_rn(a, b);
    return *reinterpret_cast<uint32_t*>(&v);
}

// ---------------- prep kernels ----------------
__global__ void gate_k(const int* __restrict__ ids, const float* __restrict__ w,
                       float* __restrict__ gate) {
    int i = blockIdx.x * blockDim.x + threadIdx.x;
    if (i >= NT) return;
    int a = ids[2 * i] & 1, b = ids[2 * i + 1] & 1;
    float wa = w[2 * i], wb = w[2 * i + 1];
    gate[i]      = (a ? 0.f : wa) + (b ? 0.f : wb);
    gate[NT + i] = (a ? wa : 0.f) + (b ? wb : 0.f);
}

__global__ void conv_k(const float4* __restrict__ x4, uint2* __restrict__ o, size_t n4) {
    size_t i = (size_t)blockIdx.x * blockDim.x + threadIdx.x;
    if (i >= n4) return;
    float4 v = x4[i];
    uint2 r;
    r.x = pack_h2(v.x, v.y);
    r.y = pack_h2(v.z, v.w);
    o[i] = r;
}

// W [K][N] f32 -> T [N][K] fp16; both experts via blockIdx.z
__global__ void transpose_h(const float* __restrict__ W0, const float* __restrict__ W1,
                            __half* __restrict__ T0, __half* __restrict__ T1,
                            int K, int N) {
    __shared__ float tile[64][33];
    const float* W = blockIdx.z ? W1 : W0;
    __half* T = blockIdx.z ? T1 : T0;
    int k0 = blockIdx.y * 64, n0 = blockIdx.x * 32;
    int tx = threadIdx.x, ty = threadIdx.y;
    for (int r = ty; r < 64; r += 8)
        tile[r][tx] = W[(size_t)(k0 + r) * N + n0 + tx];
    __syncthreads();
    for (int rn = ty; rn < 32; rn += 8) {
        float v0 = tile[2 * tx][rn], v1 = tile[2 * tx + 1][rn];
        size_t o = ((size_t)(n0 + rn) * K + k0 + 2 * tx) >> 1;
        reinterpret_cast<uint32_t*>(T)[o] = pack_h2(v0, v1);
    }
}

// ---------------- fp16 mma.sync GEMM: CTA 128xBN_, BK=64, 512 threads ----------------
static constexpr int BM = 128, BK = 64;
static constexpr int STAGES = 4;
static constexpr int NTHR = 512;

template <int ITERS>
__device__ __forceinline__ void load_tile(uint32_t sdst, const __half* __restrict__ g,
                                          int ld, int t) {
#pragma unroll
    for (int i = 0; i < ITERS; i++) {
        uint32_t idx = t + i * NTHR;
        uint32_t r = idx >> 3, s = idx & 7;
        CP_ASYNC16(sdst + swz(r, s), g + (size_t)r * ld + s * 8);
    }
}

// EPI 0 (GEMM1 merged): Ch[row][bn+col] = fp16(gate_e[row]*GELU(v+b1_e[col']));
//                       expert e = (blockIdx.x >= n_split), col' = col - e*DF
// EPI 1 (GEMM2):        Cf = v + g0*bias0[col] + g1*bias1[col]; B switches at k_split
template <int EPI, int BN_>
__global__ void __launch_bounds__(NTHR, 1)
moe_gemm(const __half* __restrict__ A,
         const __half* __restrict__ B0, const __half* __restrict__ B1,
         const float* __restrict__ bias0, const float* __restrict__ bias1,
         const float* __restrict__ gate,
         float* __restrict__ Cf, __half* __restrict__ Ch,
         int K, int lda, int ldb, int ldc, int k_split, int n_split) {
    constexpr int WN = BN_ / 4;          // warp n-extent (4x4 warp grid)
    constexpr int NTT = BN_ / 32;        // n8 tiles per warp
    constexpr int NG = NTT / 2;          // n16 ldmatrix groups per warp
    constexpr int A_ITERS = 2;           // 128 rows x 8 segs / 512 thr
    constexpr int B_ITERS = BN_ / 64;    // BN_ rows x 8 segs / 512 thr
    constexpr int A_TILE_B = BM * 128;
    constexpr int B_TILE_B = BN_ * 128;
    constexpr int STAGE_B = A_TILE_B + B_TILE_B;
    constexpr int O_A = 0, O_B = A_TILE_B;

    extern __shared__ char smem[];
    const uint32_t sb = smem_u32(smem);
    const int t = threadIdx.x, wid = t >> 5, lid = t & 31;
    const int wm = wid >> 2, wn = wid & 3;
    const int bm = blockIdx.y * BM, bn = blockIdx.x * BN_;
    const int NC = K / BK;
    const int ex = (EPI == 0) ? (blockIdx.x >= n_split) : 0;  // GEMM1 expert id

    const __half* a_g = A + (size_t)bm * lda;

    float acc[2][NTT][4];
#pragma unroll
    for (int i = 0; i < 2; i++)
#pragma unroll
        for (int j = 0; j < NTT; j++)
#pragma unroll
            for (int q = 0; q < 4; q++) acc[i][j][q] = 0.f;

#pragma unroll
    for (int p = 0; p < STAGES - 1; p++) {
        uint32_t st = sb + p * STAGE_B;
        int e = (p >= k_split);
        int kb = (p - (e ? k_split : 0)) * BK;
        load_tile<A_ITERS>(st + O_A, a_g + p * BK, lda, t);
        load_tile<B_ITERS>(st + O_B, (e ? B1 : B0) + (size_t)bn * ldb + kb, ldb, t);
        CP_COMMIT();
    }

    const uint32_t a_r = (uint32_t)(lid & 15);
    const uint32_t a_s = (uint32_t)(lid >> 4);
    const uint32_t b_r = (uint32_t)((lid & 7) + ((lid >> 4) << 3));
    const uint32_t b_s = (uint32_t)((lid >> 3) & 1);

    for (int c = 0; c < NC; c++) {
        CP_WAIT(STAGES - 2);
        __syncthreads();
        if (c + STAGES - 1 < NC) {
            int cc = c + STAGES - 1;
            uint32_t st = sb + (cc % STAGES) * STAGE_B;
            int e = (cc >= k_split);
            int kb = (cc - (e ? k_split : 0)) * BK;
            load_tile<A_ITERS>(st + O_A, a_g + cc * BK, lda, t);
            load_tile<B_ITERS>(st + O_B, (e ? B1 : B0) + (size_t)bn * ldb + kb, ldb, t);
        }
        CP_COMMIT();

        const uint32_t st = sb + (c % STAGES) * STAGE_B;
#pragma unroll
        for (int kk = 0; kk < 4; kk++) {
            uint32_t ah[2][4], bh[NG][4];
#pragma unroll
            for (int mt = 0; mt < 2; mt++) {
                uint32_t off = swz(wm * 32 + mt * 16 + a_r, kk * 2 + a_s);
                LDSM_X4(ah[mt][0], ah[mt][1], ah[mt][2], ah[mt][3], st + O_A + off);
            }
#pragma unroll
            for (int p = 0; p < NG; p++) {
                uint32_t off = swz(wn * WN + p * 16 + b_r, kk * 2 + b_s);
                LDSM_X4(bh[p][0], bh[p][1], bh[p][2], bh[p][3], st + O_B + off);
            }
#pragma unroll
            for (int mt = 0; mt < 2; mt++)
#pragma unroll
                for (int nt = 0; nt < NTT; nt++)
                    mma16816(acc[mt][nt], ah[mt], &bh[nt >> 1][(nt & 1) << 1]);
        }
    }

    // ---------------- epilogue ----------------
    const int lr = lid >> 2, lc = (lid & 3) << 1;
    const float* ba = (EPI == 0) ? (ex ? bias1 : bias0) : bias0;
    const int bco = (EPI == 0) ? ex * DF : 0;
#pragma unroll
    for (int mt = 0; mt < 2; mt++) {
        int row0 = bm + wm * 32 + mt * 16 + lr;
        float ga0, ga1, gb0 = 0.f, gb1 = 0.f;
        if (EPI == 0) {
            ga0 = gate[ex * NT + row0];
            ga1 = gate[ex * NT + row0 + 8];
        } else {
            ga0 = gate[row0];       ga1 = gate[row0 + 8];
            gb0 = gate[NT + row0];  gb1 = gate[NT + row0 + 8];
        }
#pragma unroll
        for (int nt = 0; nt < NTT; nt++) {
            int col = bn + wn * WN + nt * 8 + lc;
            float b00 = ba[col - bco], b01 = ba[col - bco + 1];
            float b10 = (EPI == 1) ? bias1[col] : 0.f;
            float b11 = (EPI == 1) ? bias1[col + 1] : 0.f;
#pragma unroll
            for (int h = 0; h < 2; h++) {
                int row = row0 + h * 8;
                size_t o = (size_t)row * ldc + col;
                if (EPI == 0) {
                    float g = h ? ga1 : ga0;
                    float v0 = acc[mt][nt][2 * h + 0] + b00;
                    float v1 = acc[mt][nt][2 * h + 1] + b01;
                    v0 = g * (0.5f * v0 * (1.0f + erff(v0 * 0.70710678118654752f)));
                    v1 = g * (0.5f * v1 * (1.0f + erff(v1 * 0.70710678118654752f)));
                    *reinterpret_cast<uint32_t*>(Ch + o) = pack_h2(v0, v1);
                } else {
                    float g0 = h ? ga1 : ga0, g1 = h ? gb1 : gb0;
                    float2 w;
                    w.x = acc[mt][nt][2 * h + 0] + g0 * b00 + g1 * b10;
                    w.y = acc[mt][nt][2 * h + 1] + g0 * b01 + g1 * b11;
                    *reinterpret_cast<float2*>(Cf + o) = w;
                }
            }
        }
    }
}

// ---------------- launch ----------------
extern "C" void kernel_launch(void* const* d_in, const int* in_sizes, int n_in,
                              void* d_out, int out_size) {
    const float* x   = (const float*)d_in[0];
    const int*   ids = (const int*)d_in[1];
    const float* tw  = (const float*)d_in[2];
    const float* W1[2] = {(const float*)d_in[3], (const float*)d_in[7]};
    const float* b1[2] = {(const float*)d_in[4], (const float*)d_in[8]};
    const float* W2[2] = {(const float*)d_in[5], (const float*)d_in[9]};
    const float* b2[2] = {(const float*)d_in[6], (const float*)d_in[10]};
    float* out = (float*)d_out;

    __half *X, *H, *W1t, *W2t;
    float* gate;
    cudaGetSymbolAddress((void**)&X, g_X);
    cudaGetSymbolAddress((void**)&H, g_H);
    cudaGetSymbolAddress((void**)&W1t, g_W1t);
    cudaGetSymbolAddress((void**)&W2t, g_W2t);
    cudaGetSymbolAddress((void**)&gate, g_gate);

    constexpr int SMEM1 = STAGES * (BM + 256) * 128;  // 196608
    constexpr int SMEM2 = STAGES * (BM + 128) * 128;  // 131072
    cudaFuncSetAttribute(moe_gemm<0, 256>, cudaFuncAttributeMaxDynamicSharedMemorySize, SMEM1);
    cudaFuncSetAttribute(moe_gemm<1, 128>, cudaFuncAttributeMaxDynamicSharedMemorySize, SMEM2);

    transpose_h<<<dim3(DF / 32, DM / 64, 2), dim3(32, 8)>>>(
        W1[0], W1[1], W1t, W1t + (size_t)DF * DM, DM, DF);
    transpose_h<<<dim3(DM / 32, DF / 64, 2), dim3(32, 8)>>>(
        W2[0], W2[1], W2t, W2t + (size_t)DM * DF, DF, DM);
    gate_k<<<(NT + 255) / 256, 256>>>(ids, tw, gate);
    {
        size_t n4 = (size_t)NT * DM / 4;
        conv_k<<<(unsigned)((n4 + 255) / 256), 256>>>((const float4*)x, (uint2*)X, n4);
    }

    const int BIG = 1 << 30;
    // GEMM1 merged: N = 16384 over both experts, grid (64, 64)
    moe_gemm<0, 256><<<dim3(2 * DF / 256, NT / BM), NTHR, SMEM1>>>(
        X, W1t, W1t, b1[0], b1[1], gate,
        nullptr, H, DM, DM, DM, 2 * DF, BIG, DF / 256);
    // GEMM2 combined: K = 16384, 128x128 tiles, grid (16, 64)
    moe_gemm<1, 128><<<dim3(DM / 128, NT / BM), NTHR, SMEM2>>>(
        H, W2t, W2t + (size_t)DM * DF, b2[0], b2[1], gate,
        out, nullptr, 2 * DF, 2 * DF, DF, DM, DF / BK, 0);
}

// round 10
// speedup vs baseline: 1.0423x; 1.0423x over previous
#include <cuda_runtime.h>
#include <cuda_fp16.h>
#include <cstdint>
#include <math.h>

#define DM 2048
#define DF 8192
#define NT 8192

// ---------------- scratch ----------------
__device__ __align__(256) __half g_X[(size_t)NT * DM];           // [M][K]
__device__ __align__(256) __half g_H[(size_t)NT * 2 * DF];       // [M][2*DF] gate pre-scaled
__device__ __align__(256) __half g_W1h[(size_t)DM * 2 * DF];     // [DM][2*DF]  (K x N, concat)
__device__ __align__(256) __half g_W2h[(size_t)2 * DF * DM];     // [2*DF][DM]  (K x N, stacked)
__device__ float g_gate[2 * NT];

// ---------------- helpers ----------------
__device__ __forceinline__ uint32_t smem_u32(const void* p) {
    uint32_t a;
    asm("{ .reg .u64 t; cvta.to.shared.u64 t, %1; cvt.u32.u64 %0, t; }" : "=r"(a) : "l"(p));
    return a;
}
#define CP_ASYNC16(sa, g) \
    asm volatile("cp.async.cg.shared.global [%0], [%1], 16;" :: "r"(sa), "l"(g))
#define CP_COMMIT() asm volatile("cp.async.commit_group;" ::: "memory")
#define CP_WAIT(n)  asm volatile("cp.async.wait_group %0;" :: "n"(n) : "memory")

#define LDSM_X4(r0, r1, r2, r3, a) \
    asm volatile("ldmatrix.sync.aligned.m8n8.x4.shared.b16 {%0,%1,%2,%3}, [%4];" \
                 : "=r"(r0), "=r"(r1), "=r"(r2), "=r"(r3) : "r"(a))
#define LDSM_X4T(r0, r1, r2, r3, a) \
    asm volatile("ldmatrix.sync.aligned.m8n8.x4.trans.shared.b16 {%0,%1,%2,%3}, [%4];" \
                 : "=r"(r0), "=r"(r1), "=r"(r2), "=r"(r3) : "r"(a))

__device__ __forceinline__ void mma16816(float* d, const uint32_t* a, const uint32_t* b) {
    asm volatile(
        "mma.sync.aligned.m16n8k16.row.col.f32.f16.f16.f32 "
        "{%0,%1,%2,%3}, {%4,%5,%6,%7}, {%8,%9}, {%0,%1,%2,%3};"
        : "+f"(d[0]), "+f"(d[1]), "+f"(d[2]), "+f"(d[3])
        : "r"(a[0]), "r"(a[1]), "r"(a[2]), "r"(a[3]), "r"(b[0]), "r"(b[1]));
}

// A tiles: 128B rows (8 segs);  B tiles: 512B rows (32 segs). XOR-of-row swizzle.
__device__ __forceinline__ uint32_t swzA(uint32_t r, uint32_t s) {
    return (r << 7) + ((s ^ (r & 7)) << 4);
}
__device__ __forceinline__ uint32_t swzB(uint32_t r, uint32_t s) {
    return (r << 9) + ((s ^ (r & 7)) << 4);
}
__device__ __forceinline__ uint32_t pack_h2(float a, float b) {
    __half2 v = __floats2half2_rn(a, b);
    return *reinterpret_cast<uint32_t*>(&v);
}

// ---------------- prep kernels ----------------
__global__ void gate_k(const int* __restrict__ ids, const float* __restrict__ w,
                       float* __restrict__ gate) {
    int i = blockIdx.x * blockDim.x + threadIdx.x;
    if (i >= NT) return;
    int a = ids[2 * i] & 1, b = ids[2 * i + 1] & 1;
    float wa = w[2 * i], wb = w[2 * i + 1];
    gate[i]      = (a ? 0.f : wa) + (b ? 0.f : wb);
    gate[NT + i] = (a ? wa : 0.f) + (b ? wb : 0.f);
}

// stream convert f32 -> fp16 (4 at a time)
__global__ void conv_k(const float4* __restrict__ x4, uint2* __restrict__ o, size_t n4) {
    size_t i = (size_t)blockIdx.x * blockDim.x + threadIdx.x;
    if (i >= n4) return;
    float4 v = x4[i];
    uint2 r;
    r.x = pack_h2(v.x, v.y);
    r.y = pack_h2(v.z, v.w);
    o[i] = r;
}

// W1_e [DM][DF] f32 -> W1h [DM][2*DF] fp16 at column offset e*DF (blockIdx.z = e)
__global__ void conv_w1(const float4* __restrict__ W0, const float4* __restrict__ W1,
                        uint2* __restrict__ out) {
    size_t i = (size_t)blockIdx.x * blockDim.x + threadIdx.x;  // over DM*DF/4
    const size_t row_u4 = DF / 4;
    if (i >= (size_t)DM * row_u4) return;
    int e = blockIdx.z;
    float4 v = e ? W1[i] : W0[i];
    size_t k = i / row_u4, n4 = i % row_u4;
    uint2 r;
    r.x = pack_h2(v.x, v.y);
    r.y = pack_h2(v.z, v.w);
    out[k * (2 * DF / 4) + (size_t)e * (DF / 4) + n4] = r;
}

// W2_e [DF][DM] f32 -> W2h rows [e*DF .. e*DF+DF) (plain block copy per expert)
__global__ void conv_w2(const float4* __restrict__ W0, const float4* __restrict__ W1,
                        uint2* __restrict__ out) {
    size_t i = (size_t)blockIdx.x * blockDim.x + threadIdx.x;  // over DF*DM/4
    if (i >= (size_t)DF * DM / 4) return;
    int e = blockIdx.z;
    float4 v = e ? W1[i] : W0[i];
    uint2 r;
    r.x = pack_h2(v.x, v.y);
    r.y = pack_h2(v.z, v.w);
    out[(size_t)e * (DF * DM / 4) + i] = r;
}

// ------------- fp16 mma.sync GEMM: CTA 128x256, BK=64, 512 thr, B in [K][N] -------------
static constexpr int BM = 128, BN = 256, BK = 64;
static constexpr int STAGES = 4;
static constexpr int A_TILE_B = BM * 128;       // [M=128][K=64] fp16, 128B rows
static constexpr int B_TILE_B = BK * 512;       // [K=64][N=256] fp16, 512B rows
static constexpr int STAGE_B = A_TILE_B + B_TILE_B;   // 49152
static constexpr int SMEM_BYTES = STAGES * STAGE_B;   // 196608
static constexpr int O_A = 0, O_B = A_TILE_B;
static constexpr int NTHR = 512;

__device__ __forceinline__ void load_A(uint32_t sdst, const __half* __restrict__ g,
                                       int ld, int t) {
#pragma unroll
    for (int i = 0; i < 2; i++) {                 // 128 rows x 8 segs / 512
        uint32_t idx = t + i * NTHR;
        uint32_t r = idx >> 3, s = idx & 7;
        CP_ASYNC16(sdst + swzA(r, s), g + (size_t)r * ld + s * 8);
    }
}
__device__ __forceinline__ void load_B(uint32_t sdst, const __half* __restrict__ g,
                                       int ld, int t) {
#pragma unroll
    for (int i = 0; i < 4; i++) {                 // 64 rows x 32 segs / 512
        uint32_t idx = t + i * NTHR;
        uint32_t r = idx >> 5, s = idx & 31;
        CP_ASYNC16(sdst + swzB(r, s), g + (size_t)r * ld + s * 8);
    }
}

// EPI 0 (GEMM1): Ch[row][col] = fp16(gate_e[row]*GELU(v + b1_e[col - e*DF])), e = bx>=n_split
// EPI 1 (GEMM2): Cf[row][col] = v + g0*bias0[col] + g1*bias1[col]
template <int EPI>
__global__ void __launch_bounds__(NTHR, 1)
moe_gemm(const __half* __restrict__ A, const __half* __restrict__ B,
         const float* __restrict__ bias0, const float* __restrict__ bias1,
         const float* __restrict__ gate,
         float* __restrict__ Cf, __half* __restrict__ Ch,
         int K, int lda, int ldb, int ldc, int n_split) {
    extern __shared__ char smem[];
    const uint32_t sb = smem_u32(smem);
    const int t = threadIdx.x, wid = t >> 5, lid = t & 31;
    const int wm = wid >> 2, wn = wid & 3;        // 4x4 warps, warp tile 32x64
    const int bm = blockIdx.y * BM, bn = blockIdx.x * BN;
    const int NC = K / BK;
    const int ex = (EPI == 0) ? (blockIdx.x >= n_split) : 0;

    const __half* a_g = A + (size_t)bm * lda;
    const __half* b_g = B + bn;

    float acc[2][8][4];
#pragma unroll
    for (int i = 0; i < 2; i++)
#pragma unroll
        for (int j = 0; j < 8; j++)
#pragma unroll
            for (int q = 0; q < 4; q++) acc[i][j][q] = 0.f;

#pragma unroll
    for (int p = 0; p < STAGES - 1; p++) {
        uint32_t st = sb + p * STAGE_B;
        load_A(st + O_A, a_g + p * BK, lda, t);
        load_B(st + O_B, b_g + (size_t)p * BK * ldb, ldb, t);
        CP_COMMIT();
    }

    // A frags (non-trans, [M][K] 128B rows)
    const uint32_t a_r = (uint32_t)(lid & 15);
    const uint32_t a_s = (uint32_t)(lid >> 4);
    // B frags (trans, [K][N] 512B rows): k row + n seg per lane
    const uint32_t bk_r = (uint32_t)((lid & 7) + ((lid >> 3) & 1) * 8);
    const uint32_t bn_s = (uint32_t)(lid >> 4);

    for (int c = 0; c < NC; c++) {
        CP_WAIT(STAGES - 2);
        __syncthreads();
        if (c + STAGES - 1 < NC) {
            int cc = c + STAGES - 1;
            uint32_t st = sb + (cc % STAGES) * STAGE_B;
            load_A(st + O_A, a_g + cc * BK, lda, t);
            load_B(st + O_B, b_g + (size_t)cc * BK * ldb, ldb, t);
        }
        CP_COMMIT();

        const uint32_t st = sb + (c % STAGES) * STAGE_B;
#pragma unroll
        for (int kk = 0; kk < 4; kk++) {
            uint32_t ah[2][4], bh[4][4];
#pragma unroll
            for (int mt = 0; mt < 2; mt++) {
                uint32_t off = swzA(wm * 32 + mt * 16 + a_r, kk * 2 + a_s);
                LDSM_X4(ah[mt][0], ah[mt][1], ah[mt][2], ah[mt][3], st + O_A + off);
            }
#pragma unroll
            for (int p = 0; p < 4; p++) {   // 4 n16 groups = warp's 64 cols
                uint32_t off = swzB(kk * 16 + bk_r, wn * 8 + p * 2 + bn_s);
                LDSM_X4T(bh[p][0], bh[p][1], bh[p][2], bh[p][3], st + O_B + off);
            }
#pragma unroll
            for (int mt = 0; mt < 2; mt++)
#pragma unroll
                for (int nt = 0; nt < 8; nt++)
                    mma16816(acc[mt][nt], ah[mt], &bh[nt >> 1][(nt & 1) << 1]);
        }
    }

    // ---------------- epilogue ----------------
    const int lr = lid >> 2, lc = (lid & 3) << 1;
    const float* ba = (EPI == 0) ? (ex ? bias1 : bias0) : bias0;
    const int bco = (EPI == 0) ? ex * DF : 0;
#pragma unroll
    for (int mt = 0; mt < 2; mt++) {
        int row0 = bm + wm * 32 + mt * 16 + lr;
        float ga0, ga1, gb0 = 0.f, gb1 = 0.f;
        if (EPI == 0) {
            ga0 = gate[ex * NT + row0];
            ga1 = gate[ex * NT + row0 + 8];
        } else {
            ga0 = gate[row0];       ga1 = gate[row0 + 8];
            gb0 = gate[NT + row0];  gb1 = gate[NT + row0 + 8];
        }
#pragma unroll
        for (int nt = 0; nt < 8; nt++) {
            int col = bn + wn * 64 + nt * 8 + lc;
            float b00 = ba[col - bco], b01 = ba[col - bco + 1];
            float b10 = (EPI == 1) ? bias1[col] : 0.f;
            float b11 = (EPI == 1) ? bias1[col + 1] : 0.f;
#pragma unroll
            for (int h = 0; h < 2; h++) {
                int row = row0 + h * 8;
                size_t o = (size_t)row * ldc + col;
                if (EPI == 0) {
                    float g = h ? ga1 : ga0;
                    float v0 = acc[mt][nt][2 * h + 0] + b00;
                    float v1 = acc[mt][nt][2 * h + 1] + b01;
                    v0 = g * (0.5f * v0 * (1.0f + erff(v0 * 0.70710678118654752f)));
                    v1 = g * (0.5f * v1 * (1.0f + erff(v1 * 0.70710678118654752f)));
                    *reinterpret_cast<uint32_t*>(Ch + o) = pack_h2(v0, v1);
                } else {
                    float g0 = h ? ga1 : ga0, g1 = h ? gb1 : gb0;
                    float2 w;
                    w.x = acc[mt][nt][2 * h + 0] + g0 * b00 + g1 * b10;
                    w.y = acc[mt][nt][2 * h + 1] + g0 * b01 + g1 * b11;
                    *reinterpret_cast<float2*>(Cf + o) = w;
                }
            }
        }
    }
}

// ---------------- launch ----------------
extern "C" void kernel_launch(void* const* d_in, const int* in_sizes, int n_in,
                              void* d_out, int out_size) {
    const float* x   = (const float*)d_in[0];
    const int*   ids = (const int*)d_in[1];
    const float* tw  = (const float*)d_in[2];
    const float* W1[2] = {(const float*)d_in[3], (const float*)d_in[7]};
    const float* b1[2] = {(const float*)d_in[4], (const float*)d_in[8]};
    const float* W2[2] = {(const float*)d_in[5], (const float*)d_in[9]};
    const float* b2[2] = {(const float*)d_in[6], (const float*)d_in[10]};
    float* out = (float*)d_out;

    __half *X, *H, *W1h, *W2h;
    float* gate;
    cudaGetSymbolAddress((void**)&X, g_X);
    cudaGetSymbolAddress((void**)&H, g_H);
    cudaGetSymbolAddress((void**)&W1h, g_W1h);
    cudaGetSymbolAddress((void**)&W2h, g_W2h);
    cudaGetSymbolAddress((void**)&gate, g_gate);

    cudaFuncSetAttribute(moe_gemm<0>, cudaFuncAttributeMaxDynamicSharedMemorySize, SMEM_BYTES);
    cudaFuncSetAttribute(moe_gemm<1>, cudaFuncAttributeMaxDynamicSharedMemorySize, SMEM_BYTES);

    // 1: gate   2: conv X   3: conv W1   4: GEMM1 (ncu slot)   5: conv W2   6: GEMM2
    gate_k<<<(NT + 255) / 256, 256>>>(ids, tw, gate);
    {
        size_t n4 = (size_t)NT * DM / 4;
        conv_k<<<(unsigned)((n4 + 255) / 256), 256>>>((const float4*)x, (uint2*)X, n4);
    }
    {
        size_t n4 = (size_t)DM * DF / 4;
        conv_w1<<<dim3((unsigned)((n4 + 255) / 256), 1, 2), 256>>>(
            (const float4*)W1[0], (const float4*)W1[1], (uint2*)W1h);
    }
    // GEMM1 merged: C = H [NT][2*DF], N = 16384, K = DM
    moe_gemm<0><<<dim3(2 * DF / BN, NT / BM), NTHR, SMEM_BYTES>>>(
        X, W1h, b1[0], b1[1], gate, nullptr, H,
        DM, DM, 2 * DF, 2 * DF, DF / BN);
    {
        size_t n4 = (size_t)DF * DM / 4;
        conv_w2<<<dim3((unsigned)((n4 + 255) / 256), 1, 2), 256>>>(
            (const float4*)W2[0], (const float4*)W2[1], (uint2*)W2h);
    }
    // GEMM2 combined: out = H @ W2h + gated biases, K = 2*DF
    moe_gemm<1><<<dim3(DM / BN, NT / BM), NTHR, SMEM_BYTES>>>(
        H, W2h, b2[0], b2[1], gate, out, nullptr,
        2 * DF, 2 * DF, DM, DM, 1 << 30);
}